// round 15
// baseline (speedup 1.0000x reference)
#include <cuda_runtime.h>
#include <cuda_fp16.h>
#include <cuda_bf16.h>
#include <cstdint>

// ---------------------------------------------------------------------------
// EstimateAdj:
//   h    = relu(features @ W1 + b1)   [N,128]->[N,64]
//   reps = h @ W2 + b2                [N,64]
//   pw[e] = relu(dot(reps[ei0[e]], reps[ei1[e]]))  e < Eo
// Output (float32 concat): reps | pw | total_edge_index | edge_index
//
// R15 vs R14 (64.2us): move the index-copy role from the MLP launch (where
// copy blocks inherited 44.5KB smem + launch_bounds(256,3) -> throttled) to
// the edge launch (0 smem, full occupancy, and the copy's DRAM traffic hides
// under the L2-bound gather: edge DRAM was at 10%).
// prep / MLP body / edge body unchanged.
// ---------------------------------------------------------------------------

#define MLP_THREADS 256
#define NODES_PER_BLK 128
#define N_MAX 100000

typedef unsigned int u32;

// fp16 shadow of reps (32 half2 per node = 128B/row) for the edge gather
__device__ __half2 g_reps_h[N_MAX * 32];

// Pre-converted weight planes, laid out exactly like the smem image:
//  [0, 17408)      Wt1h [64][136] f16
//  [17408, 34816)  Wt1l [64][136] f16
//  [34816, 44032)  Wt2h [64][72]  f16
#define WPACK_BYTES 44032
__device__ __align__(16) unsigned char g_wpack[WPACK_BYTES];

// smem layout (bytes):
//  Wt1h/Wt1l/Wt2h: as g_wpack         } GEMM phase
//  b1s [64] f32 : 44032 .. 44288      (never overwritten)
//  b2s [64] f32 : 44288 .. 44544
//  rstage [128][68] f32 : 0 .. 34816  } epilogue phase (reuses Wt1)
#define SMEM_BYTES 44544
#define W1_STRIDE 136   // elements; 68 words/row -> (68*(8n+g)+t)%32 = (4g+t)%32
#define W2_STRIDE 72    // elements; 36 words/row -> same property
#define RSTAGE_STRIDE 68   // floats; 68%32=4 -> conflict-free stage writes

__device__ __forceinline__ void mma_f16(float* c, const u32* a, u32 b0, u32 b1) {
    asm volatile(
        "mma.sync.aligned.m16n8k16.row.col.f32.f16.f16.f32 "
        "{%0,%1,%2,%3}, {%4,%5,%6,%7}, {%8,%9}, {%0,%1,%2,%3};"
        : "+f"(c[0]), "+f"(c[1]), "+f"(c[2]), "+f"(c[3])
        : "r"(a[0]), "r"(a[1]), "r"(a[2]), "r"(a[3]), "r"(b0), "r"(b1));
}

__device__ __forceinline__ u32 pack2h(float x, float y) {
    __half2 h = __floats2half2_rn(x, y);
    return *(u32*)&h;
}

// One-shot: convert W1 (fp16 hi/lo split) and W2 (single fp16) into g_wpack.
__global__ void __launch_bounds__(256)
weight_prep_kernel(const float* __restrict__ W1, const float* __restrict__ W2)
{
    int idx = blockIdx.x * 256 + threadIdx.x;
    __half* w1h = (__half*)(g_wpack);
    __half* w1l = (__half*)(g_wpack + 17408);
    __half* w2h = (__half*)(g_wpack + 34816);
    if (idx < 128 * 64) {
        int k = idx >> 6, n = idx & 63;
        float w = W1[idx];
        __half hi = __float2half_rn(w);
        w1h[n * W1_STRIDE + k] = hi;
        w1l[n * W1_STRIDE + k] = __float2half_rn(w - __half2float(hi));
    } else {
        int j = idx - 128 * 64;   // [0, 4096)
        int k = j >> 6, n = j & 63;
        w2h[n * W2_STRIDE + k] = __float2half_rn(W2[j]);
    }
}

// Pure MMA MLP.
__global__ void __launch_bounds__(MLP_THREADS, 3)
mlp_mma_kernel(const float* __restrict__ feat,
               const float* __restrict__ b1, const float* __restrict__ b2,
               float* __restrict__ reps, int N)
{
    const int tx = threadIdx.x;

    extern __shared__ char smc[];
    __half* Wt1h = (__half*)(smc);
    __half* Wt1l = (__half*)(smc + 17408);
    __half* Wt2h = (__half*)(smc + 34816);
    float* b1s = (float*)(smc + 44032);
    float* b2s = (float*)(smc + 44288);

    // Prologue: bulk-copy pre-converted weight planes (uint4, coalesced).
    {
        const uint4* src = (const uint4*)g_wpack;
        uint4* dst = (uint4*)smc;
        #pragma unroll
        for (int i = 0; i < WPACK_BYTES / 16 / MLP_THREADS + 1; i++) {
            int j = tx + i * MLP_THREADS;
            if (j < WPACK_BYTES / 16) dst[j] = src[j];
        }
    }
    if (tx < 64) { b1s[tx] = b1[tx]; b2s[tx] = b2[tx]; }
    __syncthreads();

    const int warp = tx >> 5, lane = tx & 31;
    const int g = lane >> 2, t = lane & 3;
    const int r0 = blockIdx.x * NODES_PER_BLK + warp * 16 + g;
    const int r1 = r0 + 8;
    const bool v0 = r0 < N, v1 = r1 < N;
    const float* f0p = feat + (size_t)(v0 ? r0 : 0) * 128 + t * 2;
    const float* f1p = feat + (size_t)(v1 ? r1 : 0) * 128 + t * 2;

    // ---- GEMM1: C[8 n-tiles][4] over K=128 (8 k-steps), 2-pass fp16 ----
    float C[8][4];
    #pragma unroll
    for (int n = 0; n < 8; n++)
        #pragma unroll
        for (int i = 0; i < 4; i++) C[n][i] = 0.f;

    #pragma unroll 2
    for (int kt = 0; kt < 8; kt++) {
        float2 x00 = v0 ? *(const float2*)(f0p + kt * 16)     : make_float2(0.f, 0.f);
        float2 x01 = v0 ? *(const float2*)(f0p + kt * 16 + 8) : make_float2(0.f, 0.f);
        float2 x10 = v1 ? *(const float2*)(f1p + kt * 16)     : make_float2(0.f, 0.f);
        float2 x11 = v1 ? *(const float2*)(f1p + kt * 16 + 8) : make_float2(0.f, 0.f);
        u32 ah[4];
        ah[0] = pack2h(x00.x, x00.y);
        ah[1] = pack2h(x10.x, x10.y);
        ah[2] = pack2h(x01.x, x01.y);
        ah[3] = pack2h(x11.x, x11.y);

        const int kb = kt * 16 + t * 2;
        #pragma unroll
        for (int n = 0; n < 8; n++) {
            const __half* wh = Wt1h + (n * 8 + g) * W1_STRIDE + kb;
            const __half* wl = Wt1l + (n * 8 + g) * W1_STRIDE + kb;
            u32 bh0 = *(const u32*)(wh);
            u32 bh1 = *(const u32*)(wh + 8);
            u32 bl0 = *(const u32*)(wl);
            u32 bl1 = *(const u32*)(wl + 8);
            mma_f16(C[n], ah, bh0, bh1);
            mma_f16(C[n], ah, bl0, bl1);
        }
    }

    // bias + relu -> h (registers), then pack into GEMM2 A-frags (fp16).
    #pragma unroll
    for (int n = 0; n < 8; n++) {
        float bb0 = b1s[n * 8 + t * 2];
        float bb1 = b1s[n * 8 + t * 2 + 1];
        C[n][0] = fmaxf(C[n][0] + bb0, 0.f);
        C[n][1] = fmaxf(C[n][1] + bb1, 0.f);
        C[n][2] = fmaxf(C[n][2] + bb0, 0.f);
        C[n][3] = fmaxf(C[n][3] + bb1, 0.f);
    }

    u32 a2[4][4];
    #pragma unroll
    for (int kt = 0; kt < 4; kt++) {
        a2[kt][0] = pack2h(C[2 * kt][0],     C[2 * kt][1]);
        a2[kt][1] = pack2h(C[2 * kt][2],     C[2 * kt][3]);
        a2[kt][2] = pack2h(C[2 * kt + 1][0], C[2 * kt + 1][1]);
        a2[kt][3] = pack2h(C[2 * kt + 1][2], C[2 * kt + 1][3]);
    }

    // ---- GEMM2: D[8][4] over K=64 (4 k-steps), single-pass fp16 ----
    float D[8][4];
    #pragma unroll
    for (int n = 0; n < 8; n++)
        #pragma unroll
        for (int i = 0; i < 4; i++) D[n][i] = 0.f;

    #pragma unroll
    for (int kt = 0; kt < 4; kt++) {
        const int kb = kt * 16 + t * 2;
        #pragma unroll
        for (int n = 0; n < 8; n++) {
            const __half* wh = Wt2h + (n * 8 + g) * W2_STRIDE + kb;
            u32 bh0 = *(const u32*)(wh);
            u32 bh1 = *(const u32*)(wh + 8);
            mma_f16(D[n], a2[kt], bh0, bh1);
        }
    }

    // ---- Epilogue: stage fp32 in smem (Wt1 region dead), coalesced write ----
    __syncthreads();   // all warps done reading Wt1/Wt2
    float* rstage = (float*)smc;                 // [128][68]

    const int lr0 = warp * 16 + g;
    const int lr1 = lr0 + 8;
    #pragma unroll
    for (int n = 0; n < 8; n++) {
        int c0 = n * 8 + t * 2;
        float bb0 = b2s[c0], bb1 = b2s[c0 + 1];
        rstage[lr0 * RSTAGE_STRIDE + c0]     = D[n][0] + bb0;
        rstage[lr0 * RSTAGE_STRIDE + c0 + 1] = D[n][1] + bb1;
        rstage[lr1 * RSTAGE_STRIDE + c0]     = D[n][2] + bb0;
        rstage[lr1 * RSTAGE_STRIDE + c0 + 1] = D[n][3] + bb1;
    }
    __syncthreads();

    const int base_row = blockIdx.x * NODES_PER_BLK;
    // reps: 128 rows x 16 float4, coalesced
    for (int i = tx; i < 128 * 16; i += MLP_THREADS) {
        int row = i >> 4, c = i & 15;
        int grow = base_row + row;
        if (grow < N) {
            const float* s = rstage + row * RSTAGE_STRIDE + c * 4;
            float4 v = make_float4(s[0], s[1], s[2], s[3]);
            *(float4*)(reps + (size_t)grow * 64 + c * 4) = v;
        }
    }
    // shadow: 128 rows x 8 uint4, converted from rstage, coalesced
    for (int i = tx; i < 128 * 8; i += MLP_THREADS) {
        int row = i >> 3, c = i & 7;
        int grow = base_row + row;
        if (grow < N) {
            const float* s = rstage + row * RSTAGE_STRIDE + c * 8;
            uint4 v;
            v.x = pack2h(s[0], s[1]);
            v.y = pack2h(s[2], s[3]);
            v.z = pack2h(s[4], s[5]);
            v.w = pack2h(s[6], s[7]);
            *(uint4*)(g_reps_h + (size_t)grow * 32 + c * 4) = v;
        }
    }
}

__device__ __forceinline__ float dot8h(uint4 a, uint4 b) {
    const __half2* pa = (const __half2*)&a;
    const __half2* pb = (const __half2*)&b;
    float acc = 0.f;
    #pragma unroll
    for (int j = 0; j < 4; j++) {
        float2 x = __half22float2(pa[j]);
        float2 y = __half22float2(pb[j]);
        acc = fmaf(x.x, y.x, acc);
        acc = fmaf(x.y, y.y, acc);
    }
    return acc;
}

// Edge dots (frozen body since R9) + index-copy role (0 smem, full occ;
// copy DRAM traffic hides under the L2-bound gather).
__global__ void __launch_bounds__(256)
edge_dot_plus_copy_kernel(const int* __restrict__ ei, long long Eo,
                          float* __restrict__ pw, int N, int edge_blocks,
                          const int* __restrict__ pei, long long Ec,
                          float* __restrict__ out_tei, float* __restrict__ out_ei)
{
    if (blockIdx.x >= edge_blocks) {
        // ---------------- index copy role (vectorized x4) ----------------
        const int tx = threadIdx.x;
        long long i = ((long long)(blockIdx.x - edge_blocks) * 256 + tx) * 4;
        long long Et = Eo + Ec;
        if (i < Eo) {
            int4 v0 = *(const int4*)(ei + i);
            int4 v1 = *(const int4*)(ei + Eo + i);
            float4 f0 = make_float4((float)v0.x, (float)v0.y, (float)v0.z, (float)v0.w);
            float4 f1 = make_float4((float)v1.x, (float)v1.y, (float)v1.z, (float)v1.w);
            *(float4*)(out_tei + i)      = f0;
            *(float4*)(out_tei + Et + i) = f1;
            *(float4*)(out_ei + i)       = f0;
            *(float4*)(out_ei + Eo + i)  = f1;
        }
        if (i < Ec) {
            int4 v0 = *(const int4*)(pei + i);
            int4 v1 = *(const int4*)(pei + Ec + i);
            float4 f0 = make_float4((float)v0.x, (float)v0.y, (float)v0.z, (float)v0.w);
            float4 f1 = make_float4((float)v1.x, (float)v1.y, (float)v1.z, (float)v1.w);
            *(float4*)(out_tei + Eo + i)      = f0;
            *(float4*)(out_tei + Et + Eo + i) = f1;
        }
        return;
    }

    // ---------------- edge dot role ----------------
    const int lane = threadIdx.x & 31;
    const int sub = lane & 7;      // 16B chunk within the 128B row
    const int g = lane >> 3;       // edge slot within warp (0..3)
    long long warp_g = ((long long)blockIdx.x * blockDim.x + threadIdx.x) >> 5;
    long long ebase = warp_g * 16;
    if (ebase >= Eo) return;

    int i0[4], i1[4];
    #pragma unroll
    for (int j = 0; j < 4; j++) {
        long long e = ebase + j * 4 + g;
        int a = (e < Eo) ? ei[e] : 0;
        int b = (e < Eo) ? ei[e + Eo] : 0;
        i0[j] = min(max(a, 0), N - 1);
        i1[j] = min(max(b, 0), N - 1);
    }

    uint4 av[4], bv[4];
    #pragma unroll
    for (int j = 0; j < 4; j++) {
        av[j] = ((const uint4*)(g_reps_h + (size_t)i0[j] * 32))[sub];
        bv[j] = ((const uint4*)(g_reps_h + (size_t)i1[j] * 32))[sub];
    }

    float acc[4];
    #pragma unroll
    for (int j = 0; j < 4; j++) {
        acc[j] = dot8h(av[j], bv[j]);
        acc[j] += __shfl_xor_sync(0xffffffffu, acc[j], 4);
        acc[j] += __shfl_xor_sync(0xffffffffu, acc[j], 2);
        acc[j] += __shfl_xor_sync(0xffffffffu, acc[j], 1);
    }

    if (sub == 0) {
        #pragma unroll
        for (int j = 0; j < 4; j++) {
            long long e = ebase + j * 4 + g;
            if (e < Eo) pw[e] = fmaxf(acc[j], 0.f);
        }
    }
}

extern "C" void kernel_launch(void* const* d_in, const int* in_sizes, int n_in,
                              void* d_out, int out_size)
{
    const float* feat = (const float*)d_in[0];
    const int*   ei   = (const int*)d_in[1];
    const int*   pei  = (const int*)d_in[2];
    const float* W1   = (const float*)d_in[3];
    const float* b1   = (const float*)d_in[4];
    const float* W2   = (const float*)d_in[5];
    const float* b2   = (const float*)d_in[6];
    float* out = (float*)d_out;

    const int N        = in_sizes[0] / 128;
    const long long Eo = in_sizes[1] / 2;
    const long long Ec = in_sizes[2] / 2;

    float* reps    = out;
    float* pw      = out + (size_t)N * 64;
    float* out_tei = pw + Eo;
    float* out_ei  = out_tei + 2 * (Eo + Ec);

    cudaFuncSetAttribute(mlp_mma_kernel,
                         cudaFuncAttributeMaxDynamicSharedMemorySize, SMEM_BYTES);

    // One-shot weight conversion
    weight_prep_kernel<<<48, 256>>>(W1, W2);

    // Pure MLP
    int mlp_blocks = (N + NODES_PER_BLK - 1) / NODES_PER_BLK;
    mlp_mma_kernel<<<mlp_blocks, MLP_THREADS, SMEM_BYTES>>>(
        feat, b1, b2, reps, N);

    // Edge dots + index copy
    long long warps = (Eo + 15) / 16;
    long long threads = warps * 32;
    int edge_blocks = (int)((threads + 255) / 256);
    long long copy_items = (Eo > Ec ? Eo : Ec);
    int copy_blocks = (int)((copy_items + 256LL * 4 - 1) / (256LL * 4));

    edge_dot_plus_copy_kernel<<<edge_blocks + copy_blocks, 256>>>(
        ei, Eo, pw, N, edge_blocks, pei, Ec, out_tei, out_ei);
}

// round 16
// speedup vs baseline: 1.0947x; 1.0947x over previous
#include <cuda_runtime.h>
#include <cuda_fp16.h>
#include <cuda_bf16.h>
#include <cstdint>

// ---------------------------------------------------------------------------
// EstimateAdj:
//   h    = relu(features @ W1 + b1)   [N,128]->[N,64]
//   reps = h @ W2 + b2                [N,64]
//   pw[e] = relu(dot(reps[ei0[e]], reps[ei1[e]]))  e < Eo
// Output (float32 concat): reps | pw | total_edge_index | edge_index
//
// R16: revert to R14 arrangement (copy role in MLP launch — R15 showed the
// copy does NOT hide under the L2-saturated edge kernel), plus:
//  - W1 single fp16 (drop the lo plane): GEMM1 MMAs halved, wpack 44->26.6KB,
//    smem 44.5->35.3KB. rel_err budget: +~1.4e-4 in quadrature.
// prep / edge bodies unchanged (edge at LTS cap = floor).
// ---------------------------------------------------------------------------

#define MLP_THREADS 256
#define NODES_PER_BLK 128
#define N_MAX 100000

typedef unsigned int u32;

// fp16 shadow of reps (32 half2 per node = 128B/row) for the edge gather
__device__ __half2 g_reps_h[N_MAX * 32];

// Pre-converted weight planes, laid out exactly like the smem image:
//  [0, 17408)      Wt1h [64][136] f16
//  [17408, 26624)  Wt2h [64][72]  f16
#define WPACK_BYTES 26624
__device__ __align__(16) unsigned char g_wpack[WPACK_BYTES];

// smem layout (bytes):
//  Wt1h/Wt2h: as g_wpack              } GEMM phase
//  rstage [128][68] f32 : 0 .. 34816  } epilogue phase (overlaps weights)
//  b1s [64] f32 : 34816 .. 35072      (never overwritten)
//  b2s [64] f32 : 35072 .. 35328
#define SMEM_BYTES 35328
#define W1_STRIDE 136   // elements; 68 words/row -> (68*(8n+g)+t)%32 = (4g+t)%32
#define W2_STRIDE 72    // elements; 36 words/row -> same property
#define RSTAGE_STRIDE 68   // floats; 68%32=4 -> conflict-free stage writes

__device__ __forceinline__ void mma_f16(float* c, const u32* a, u32 b0, u32 b1) {
    asm volatile(
        "mma.sync.aligned.m16n8k16.row.col.f32.f16.f16.f32 "
        "{%0,%1,%2,%3}, {%4,%5,%6,%7}, {%8,%9}, {%0,%1,%2,%3};"
        : "+f"(c[0]), "+f"(c[1]), "+f"(c[2]), "+f"(c[3])
        : "r"(a[0]), "r"(a[1]), "r"(a[2]), "r"(a[3]), "r"(b0), "r"(b1));
}

__device__ __forceinline__ u32 pack2h(float x, float y) {
    __half2 h = __floats2half2_rn(x, y);
    return *(u32*)&h;
}

// One-shot: convert W1, W2 to single-fp16 transposed planes in g_wpack.
__global__ void __launch_bounds__(256)
weight_prep_kernel(const float* __restrict__ W1, const float* __restrict__ W2)
{
    int idx = blockIdx.x * 256 + threadIdx.x;
    __half* w1h = (__half*)(g_wpack);
    __half* w2h = (__half*)(g_wpack + 17408);
    if (idx < 128 * 64) {
        int k = idx >> 6, n = idx & 63;
        w1h[n * W1_STRIDE + k] = __float2half_rn(W1[idx]);
    } else {
        int j = idx - 128 * 64;   // [0, 4096)
        int k = j >> 6, n = j & 63;
        w2h[n * W2_STRIDE + k] = __float2half_rn(W2[j]);
    }
}

// MMA MLP + (role-split) index copy.
__global__ void __launch_bounds__(MLP_THREADS, 3)
mlp_mma_kernel(const float* __restrict__ feat,
               const float* __restrict__ b1, const float* __restrict__ b2,
               float* __restrict__ reps, int N, int mlp_blocks,
               const int* __restrict__ ei, const int* __restrict__ pei,
               long long Eo, long long Ec,
               float* __restrict__ out_tei, float* __restrict__ out_ei)
{
    const int tx = threadIdx.x;

    if (blockIdx.x >= mlp_blocks) {
        // ---------------- index copy role (vectorized x4) ----------------
        long long i = ((long long)(blockIdx.x - mlp_blocks) * MLP_THREADS + tx) * 4;
        long long Et = Eo + Ec;
        if (i < Eo) {
            int4 v0 = *(const int4*)(ei + i);
            int4 v1 = *(const int4*)(ei + Eo + i);
            float4 f0 = make_float4((float)v0.x, (float)v0.y, (float)v0.z, (float)v0.w);
            float4 f1 = make_float4((float)v1.x, (float)v1.y, (float)v1.z, (float)v1.w);
            *(float4*)(out_tei + i)      = f0;
            *(float4*)(out_tei + Et + i) = f1;
            *(float4*)(out_ei + i)       = f0;
            *(float4*)(out_ei + Eo + i)  = f1;
        }
        if (i < Ec) {
            int4 v0 = *(const int4*)(pei + i);
            int4 v1 = *(const int4*)(pei + Ec + i);
            float4 f0 = make_float4((float)v0.x, (float)v0.y, (float)v0.z, (float)v0.w);
            float4 f1 = make_float4((float)v1.x, (float)v1.y, (float)v1.z, (float)v1.w);
            *(float4*)(out_tei + Eo + i)      = f0;
            *(float4*)(out_tei + Et + Eo + i) = f1;
        }
        return;
    }

    // ---------------- MLP role ----------------
    extern __shared__ char smc[];
    __half* Wt1h = (__half*)(smc);
    __half* Wt2h = (__half*)(smc + 17408);
    float* b1s = (float*)(smc + 34816);
    float* b2s = (float*)(smc + 35072);

    // Prologue: bulk-copy pre-converted weight planes (uint4, coalesced).
    {
        const uint4* src = (const uint4*)g_wpack;
        uint4* dst = (uint4*)smc;
        #pragma unroll
        for (int i = 0; i < WPACK_BYTES / 16 / MLP_THREADS + 1; i++) {
            int j = tx + i * MLP_THREADS;
            if (j < WPACK_BYTES / 16) dst[j] = src[j];
        }
    }
    if (tx < 64) { b1s[tx] = b1[tx]; b2s[tx] = b2[tx]; }
    __syncthreads();

    const int warp = tx >> 5, lane = tx & 31;
    const int g = lane >> 2, t = lane & 3;
    const int r0 = blockIdx.x * NODES_PER_BLK + warp * 16 + g;
    const int r1 = r0 + 8;
    const bool v0 = r0 < N, v1 = r1 < N;
    const float* f0p = feat + (size_t)(v0 ? r0 : 0) * 128 + t * 2;
    const float* f1p = feat + (size_t)(v1 ? r1 : 0) * 128 + t * 2;

    // ---- GEMM1: C[8 n-tiles][4] over K=128 (8 k-steps), single-pass fp16 ----
    float C[8][4];
    #pragma unroll
    for (int n = 0; n < 8; n++)
        #pragma unroll
        for (int i = 0; i < 4; i++) C[n][i] = 0.f;

    #pragma unroll 2
    for (int kt = 0; kt < 8; kt++) {
        float2 x00 = v0 ? *(const float2*)(f0p + kt * 16)     : make_float2(0.f, 0.f);
        float2 x01 = v0 ? *(const float2*)(f0p + kt * 16 + 8) : make_float2(0.f, 0.f);
        float2 x10 = v1 ? *(const float2*)(f1p + kt * 16)     : make_float2(0.f, 0.f);
        float2 x11 = v1 ? *(const float2*)(f1p + kt * 16 + 8) : make_float2(0.f, 0.f);
        u32 ah[4];
        ah[0] = pack2h(x00.x, x00.y);
        ah[1] = pack2h(x10.x, x10.y);
        ah[2] = pack2h(x01.x, x01.y);
        ah[3] = pack2h(x11.x, x11.y);

        const int kb = kt * 16 + t * 2;
        #pragma unroll
        for (int n = 0; n < 8; n++) {
            const __half* wh = Wt1h + (n * 8 + g) * W1_STRIDE + kb;
            u32 bh0 = *(const u32*)(wh);
            u32 bh1 = *(const u32*)(wh + 8);
            mma_f16(C[n], ah, bh0, bh1);
        }
    }

    // bias + relu -> h (registers), then pack into GEMM2 A-frags (fp16).
    #pragma unroll
    for (int n = 0; n < 8; n++) {
        float bb0 = b1s[n * 8 + t * 2];
        float bb1 = b1s[n * 8 + t * 2 + 1];
        C[n][0] = fmaxf(C[n][0] + bb0, 0.f);
        C[n][1] = fmaxf(C[n][1] + bb1, 0.f);
        C[n][2] = fmaxf(C[n][2] + bb0, 0.f);
        C[n][3] = fmaxf(C[n][3] + bb1, 0.f);
    }

    u32 a2[4][4];
    #pragma unroll
    for (int kt = 0; kt < 4; kt++) {
        a2[kt][0] = pack2h(C[2 * kt][0],     C[2 * kt][1]);
        a2[kt][1] = pack2h(C[2 * kt][2],     C[2 * kt][3]);
        a2[kt][2] = pack2h(C[2 * kt + 1][0], C[2 * kt + 1][1]);
        a2[kt][3] = pack2h(C[2 * kt + 1][2], C[2 * kt + 1][3]);
    }

    // ---- GEMM2: D[8][4] over K=64 (4 k-steps), single-pass fp16 ----
    float D[8][4];
    #pragma unroll
    for (int n = 0; n < 8; n++)
        #pragma unroll
        for (int i = 0; i < 4; i++) D[n][i] = 0.f;

    #pragma unroll
    for (int kt = 0; kt < 4; kt++) {
        const int kb = kt * 16 + t * 2;
        #pragma unroll
        for (int n = 0; n < 8; n++) {
            const __half* wh = Wt2h + (n * 8 + g) * W2_STRIDE + kb;
            u32 bh0 = *(const u32*)(wh);
            u32 bh1 = *(const u32*)(wh + 8);
            mma_f16(D[n], a2[kt], bh0, bh1);
        }
    }

    // ---- Epilogue: stage fp32 in smem (weight region dead), coalesced write ----
    __syncthreads();   // all warps done reading Wt1/Wt2
    float* rstage = (float*)smc;                 // [128][68]

    const int lr0 = warp * 16 + g;
    const int lr1 = lr0 + 8;
    #pragma unroll
    for (int n = 0; n < 8; n++) {
        int c0 = n * 8 + t * 2;
        float bb0 = b2s[c0], bb1 = b2s[c0 + 1];
        rstage[lr0 * RSTAGE_STRIDE + c0]     = D[n][0] + bb0;
        rstage[lr0 * RSTAGE_STRIDE + c0 + 1] = D[n][1] + bb1;
        rstage[lr1 * RSTAGE_STRIDE + c0]     = D[n][2] + bb0;
        rstage[lr1 * RSTAGE_STRIDE + c0 + 1] = D[n][3] + bb1;
    }
    __syncthreads();

    const int base_row = blockIdx.x * NODES_PER_BLK;
    // reps: 128 rows x 16 float4, coalesced
    for (int i = tx; i < 128 * 16; i += MLP_THREADS) {
        int row = i >> 4, c = i & 15;
        int grow = base_row + row;
        if (grow < N) {
            const float* s = rstage + row * RSTAGE_STRIDE + c * 4;
            float4 v = make_float4(s[0], s[1], s[2], s[3]);
            *(float4*)(reps + (size_t)grow * 64 + c * 4) = v;
        }
    }
    // shadow: 128 rows x 8 uint4, converted from rstage, coalesced
    for (int i = tx; i < 128 * 8; i += MLP_THREADS) {
        int row = i >> 3, c = i & 7;
        int grow = base_row + row;
        if (grow < N) {
            const float* s = rstage + row * RSTAGE_STRIDE + c * 8;
            uint4 v;
            v.x = pack2h(s[0], s[1]);
            v.y = pack2h(s[2], s[3]);
            v.z = pack2h(s[4], s[5]);
            v.w = pack2h(s[6], s[7]);
            *(uint4*)(g_reps_h + (size_t)grow * 32 + c * 4) = v;
        }
    }
}

__device__ __forceinline__ float dot8h(uint4 a, uint4 b) {
    const __half2* pa = (const __half2*)&a;
    const __half2* pb = (const __half2*)&b;
    float acc = 0.f;
    #pragma unroll
    for (int j = 0; j < 4; j++) {
        float2 x = __half22float2(pa[j]);
        float2 y = __half22float2(pb[j]);
        acc = fmaf(x.x, y.x, acc);
        acc = fmaf(x.y, y.y, acc);
    }
    return acc;
}

// Edge dots (frozen since R9): 8 lanes/edge, 4 edges/thread.
__global__ void __launch_bounds__(256)
edge_dot_kernel(const int* __restrict__ ei, long long Eo,
                float* __restrict__ pw, int N)
{
    const int lane = threadIdx.x & 31;
    const int sub = lane & 7;      // 16B chunk within the 128B row
    const int g = lane >> 3;       // edge slot within warp (0..3)
    long long warp_g = ((long long)blockIdx.x * blockDim.x + threadIdx.x) >> 5;
    long long ebase = warp_g * 16;
    if (ebase >= Eo) return;

    int i0[4], i1[4];
    #pragma unroll
    for (int j = 0; j < 4; j++) {
        long long e = ebase + j * 4 + g;
        int a = (e < Eo) ? ei[e] : 0;
        int b = (e < Eo) ? ei[e + Eo] : 0;
        i0[j] = min(max(a, 0), N - 1);
        i1[j] = min(max(b, 0), N - 1);
    }

    uint4 av[4], bv[4];
    #pragma unroll
    for (int j = 0; j < 4; j++) {
        av[j] = ((const uint4*)(g_reps_h + (size_t)i0[j] * 32))[sub];
        bv[j] = ((const uint4*)(g_reps_h + (size_t)i1[j] * 32))[sub];
    }

    float acc[4];
    #pragma unroll
    for (int j = 0; j < 4; j++) {
        acc[j] = dot8h(av[j], bv[j]);
        acc[j] += __shfl_xor_sync(0xffffffffu, acc[j], 4);
        acc[j] += __shfl_xor_sync(0xffffffffu, acc[j], 2);
        acc[j] += __shfl_xor_sync(0xffffffffu, acc[j], 1);
    }

    if (sub == 0) {
        #pragma unroll
        for (int j = 0; j < 4; j++) {
            long long e = ebase + j * 4 + g;
            if (e < Eo) pw[e] = fmaxf(acc[j], 0.f);
        }
    }
}

extern "C" void kernel_launch(void* const* d_in, const int* in_sizes, int n_in,
                              void* d_out, int out_size)
{
    const float* feat = (const float*)d_in[0];
    const int*   ei   = (const int*)d_in[1];
    const int*   pei  = (const int*)d_in[2];
    const float* W1   = (const float*)d_in[3];
    const float* b1   = (const float*)d_in[4];
    const float* W2   = (const float*)d_in[5];
    const float* b2   = (const float*)d_in[6];
    float* out = (float*)d_out;

    const int N        = in_sizes[0] / 128;
    const long long Eo = in_sizes[1] / 2;
    const long long Ec = in_sizes[2] / 2;

    float* reps    = out;
    float* pw      = out + (size_t)N * 64;
    float* out_tei = pw + Eo;
    float* out_ei  = out_tei + 2 * (Eo + Ec);

    cudaFuncSetAttribute(mlp_mma_kernel,
                         cudaFuncAttributeMaxDynamicSharedMemorySize, SMEM_BYTES);

    // One-shot weight conversion
    weight_prep_kernel<<<48, 256>>>(W1, W2);

    int mlp_blocks = (N + NODES_PER_BLK - 1) / NODES_PER_BLK;
    long long copy_items = (Eo > Ec ? Eo : Ec);
    int copy_blocks = (int)((copy_items + MLP_THREADS * 4 - 1) / (MLP_THREADS * 4));

    mlp_mma_kernel<<<mlp_blocks + copy_blocks, MLP_THREADS, SMEM_BYTES>>>(
        feat, b1, b2, reps, N, mlp_blocks,
        ei, pei, Eo, Ec, out_tei, out_ei);

    // warps of 16 edges each
    long long warps = (Eo + 15) / 16;
    long long threads = warps * 32;
    int edge_blocks = (int)((threads + 255) / 256);
    edge_dot_kernel<<<edge_blocks, 256>>>(ei, Eo, pw, N);
}